// round 9
// baseline (speedup 1.0000x reference)
#include <cuda_runtime.h>
#include <cstdint>

#define B    32
#define D    1024   // CTX_DIM
#define C    2048   // CTX_SIZE
#define H    1024   // HID
#define HC   32     // h-chunks in kernel A
#define HCH  (H/HC) // 32 h per chunk
#define CCH  16     // context columns per chunk
#define GCH  16     // chunks per CTA
#define NCHB (C/(CCH*GCH))  // 8 CTA-groups per batch
#define NSTAGE 3
#define TILE_F (D*CCH)       // 16384 floats = 64KB per stage

// ---- scratch (no allocations allowed) ----
__device__ float g_pv[HC * B * D];       // 4 MB  partial v
__device__ float g_v[B * D];             // 128 KB v[b,d]
__device__ float g_pacc[B * NCHB * D];   // 1 MB per-CTA weighted partial sums
__device__ float g_pm[B * NCHB];
__device__ float g_pz[B * NCHB];
__device__ float g_ctx[B * D];           // final normalized context

__device__ __forceinline__ void cp_async16(uint32_t sa, const void* ga) {
    asm volatile("cp.async.cg.shared.global [%0], [%1], 16;" :: "r"(sa), "l"(ga));
}

// ---------- Kernel A ----------
__global__ void vpart_kernel(const float* __restrict__ W, const float* __restrict__ hid) {
    __shared__ float sh[B][HCH];
    const int tid = threadIdx.x;                 // 128
    const int d   = blockIdx.x * 128 + tid;
    const int h0  = blockIdx.y * HCH;
    for (int i = tid; i < B * HCH; i += 128) {
        int b = i / HCH, h = i % HCH;
        sh[b][h] = hid[b * H + h0 + h];
    }
    __syncthreads();
    float acc[B];
#pragma unroll
    for (int b = 0; b < B; b++) acc[b] = 0.f;
#pragma unroll 8
    for (int h = 0; h < HCH; h++) {
        float w = W[(size_t)(h0 + h) * D + d];
#pragma unroll
        for (int b = 0; b < B; b++) acc[b] += w * sh[b][h];
    }
    float* outp = g_pv + (size_t)blockIdx.y * (B * D);
#pragma unroll
    for (int b = 0; b < B; b++) outp[b * D + d] = acc[b];
}

// ---------- Kernel B ----------
__global__ void vreduce_kernel() {
    int i = blockIdx.x * 256 + threadIdx.x;      // 32 x 256 -> 8192 float4
    const float4* src = reinterpret_cast<const float4*>(g_pv) + i;
    float4 s = make_float4(0.f, 0.f, 0.f, 0.f);
#pragma unroll 8
    for (int hc = 0; hc < HC; hc++) {
        float4 p = src[(size_t)hc * (B * D / 4)];
        s.x += p.x; s.y += p.y; s.z += p.z; s.w += p.w;
    }
    reinterpret_cast<float4*>(g_v)[i] = s;
}

// ---------- Kernel C: cp.async 3-stage pipelined flash accumulation ----------
extern __shared__ float smem[];
__global__ void __launch_bounds__(1024, 1) main_kernel(const float* __restrict__ ctx) {
    float* red = smem + NSTAGE * TILE_F;   // 32*17 floats

    const int tid  = threadIdx.x;       // 1024
    const int lane = tid & 31;
    const int w    = tid >> 5;          // 0..31
    const int cq   = lane & 3;
    const int r    = lane >> 2;         // 0..7
    const int colh = lane & 15;
    const int half = lane >> 4;
    const int b    = blockIdx.y;
    const int grp  = blockIdx.x;        // 0..NCHB-1
    const int drow = w * 8 + r;         // 0..255

    const float* cbase = ctx + (size_t)b * D * C + grp * (CCH * GCH);
    const uint32_t sbase = (uint32_t)__cvta_generic_to_shared(smem);
    const int rowi = tid >> 2;          // 0..255, load row within 256-row group
    const int colq = tid & 3;           // 16B column quarter

    float vr[4];
#pragma unroll
    for (int i = 0; i < 4; i++)
        vr[i] = __ldg(&g_v[b * D + i * 256 + drow]);

    float accR[4] = {0.f, 0.f, 0.f, 0.f};
    float m_run = -1e30f, z_run = 0.f;

    // ---- prologue: fill 3 stages ----
#pragma unroll
    for (int s = 0; s < NSTAGE; s++) {
        const float* src = cbase + s * CCH;
        uint32_t dst = sbase + (uint32_t)s * (TILE_F * 4);
#pragma unroll
        for (int k = 0; k < 4; k++) {
            int row = k * 256 + rowi;
            cp_async16(dst + row * 64 + colq * 16, src + (size_t)row * C + colq * 4);
        }
        asm volatile("cp.async.commit_group;");
    }

    for (int g = 0; g < GCH; g++) {
        if (g < GCH - 2)      asm volatile("cp.async.wait_group 2;");
        else if (g == GCH - 2) asm volatile("cp.async.wait_group 1;");
        else                   asm volatile("cp.async.wait_group 0;");
        __syncthreads();

        const float* tile = smem + (g % NSTAGE) * TILE_F;
        float4 x[4];
#pragma unroll
        for (int i = 0; i < 4; i++)
            x[i] = *reinterpret_cast<const float4*>(tile + (i * 256 + drow) * 16 + cq * 4);

        // Phase 1: partial scores (this warp's 32 rows)
        float p0 = 0.f, p1 = 0.f, p2 = 0.f, p3 = 0.f;
#pragma unroll
        for (int i = 0; i < 4; i++) {
            p0 += x[i].x * vr[i];  p1 += x[i].y * vr[i];
            p2 += x[i].z * vr[i];  p3 += x[i].w * vr[i];
        }
#pragma unroll
        for (int o = 4; o <= 16; o <<= 1) {
            p0 += __shfl_xor_sync(0xffffffffu, p0, o);
            p1 += __shfl_xor_sync(0xffffffffu, p1, o);
            p2 += __shfl_xor_sync(0xffffffffu, p2, o);
            p3 += __shfl_xor_sync(0xffffffffu, p3, o);
        }
        if (lane < 4) {
            red[w * 17 + 4 * lane + 0] = p0;
            red[w * 17 + 4 * lane + 1] = p1;
            red[w * 17 + 4 * lane + 2] = p2;
            red[w * 17 + 4 * lane + 3] = p3;
        }
        __syncthreads();

        // Every warp redundantly: column sums over 32 warps + softmax stats
        float part = 0.f;
#pragma unroll
        for (int j = 0; j < 16; j++)
            part += red[(half * 16 + j) * 17 + colh];
        part += __shfl_xor_sync(0xffffffffu, part, 16);
        float m = part;
#pragma unroll
        for (int o = 1; o <= 8; o <<= 1) m = fmaxf(m, __shfl_xor_sync(0xffffffffu, m, o));
        float e = __expf(part - m);
        float z = e;
#pragma unroll
        for (int o = 1; o <= 8; o <<= 1) z += __shfl_xor_sync(0xffffffffu, z, o);

        const float w0 = __shfl_sync(0xffffffffu, e, 4 * cq + 0, 16);
        const float w1 = __shfl_sync(0xffffffffu, e, 4 * cq + 1, 16);
        const float w2 = __shfl_sync(0xffffffffu, e, 4 * cq + 2, 16);
        const float w3 = __shfl_sync(0xffffffffu, e, 4 * cq + 3, 16);

        // Phase 2 + running rescale (register-resident)
        const float m_new = fmaxf(m_run, m);
        const float alpha = __expf(m_run - m_new);
        const float beta  = __expf(m - m_new);
#pragma unroll
        for (int i = 0; i < 4; i++) {
            float t = x[i].x * w0 + x[i].y * w1 + x[i].z * w2 + x[i].w * w3;
            t += __shfl_xor_sync(0xffffffffu, t, 1);
            t += __shfl_xor_sync(0xffffffffu, t, 2);
            accR[i] = accR[i] * alpha + t * beta;
        }
        z_run = z_run * alpha + z * beta;
        m_run = m_new;
        __syncthreads();     // red WAR + tile WAR before refill

        if (g + NSTAGE < GCH) {
            const int gn = g + NSTAGE;
            const float* src = cbase + gn * CCH;
            uint32_t dst = sbase + (uint32_t)(g % NSTAGE) * (TILE_F * 4);
#pragma unroll
            for (int k = 0; k < 4; k++) {
                int row = k * 256 + rowi;
                cp_async16(dst + row * 64 + colq * 16, src + (size_t)row * C + colq * 4);
            }
            asm volatile("cp.async.commit_group;");
        }
    }

    if (cq == 0) {
        float* dst = g_pacc + (size_t)(b * NCHB + grp) * D;
#pragma unroll
        for (int i = 0; i < 4; i++) dst[i * 256 + drow] = accR[i];
    }
    if (tid == 0) { g_pm[b * NCHB + grp] = m_run; g_pz[b * NCHB + grp] = z_run; }
}

// ---------- Kernel D1: combine 8 chunk partials -> g_ctx ----------
__global__ void combine_kernel() {
    __shared__ float pm[NCHB], pz[NCHB], fsh[NCHB];
    __shared__ float inv_sh;
    __shared__ float4 part[8][32];
    const int b   = blockIdx.x;
    const int ds  = blockIdx.y;            // 0..7 d-slice (128 d's)
    const int tid = threadIdx.x;           // 256
    const int f4  = tid & 31;
    const int grp = tid >> 5;              // 0..7 = chunk entry

    if (tid < NCHB) { pm[tid] = g_pm[b * NCHB + tid]; pz[tid] = g_pz[b * NCHB + tid]; }
    __syncthreads();
    if (tid < NCHB) {
        float M = -1e30f;
#pragma unroll
        for (int ch = 0; ch < NCHB; ch++) M = fmaxf(M, pm[ch]);
        fsh[tid] = __expf(pm[tid] - M);
        if (tid == 0) {
            float Z = 0.f;
#pragma unroll
            for (int ch = 0; ch < NCHB; ch++) Z += pz[ch] * __expf(pm[ch] - M);
            inv_sh = 1.0f / Z;
        }
    }
    __syncthreads();

    float4 p = reinterpret_cast<const float4*>(
        g_pacc + (size_t)(b * NCHB + grp) * D + ds * 128)[f4];
    const float f = fsh[grp];
    part[grp][f4] = make_float4(p.x * f, p.y * f, p.z * f, p.w * f);
    __syncthreads();

    if (tid < 32) {
        float4 s = make_float4(0.f, 0.f, 0.f, 0.f);
#pragma unroll
        for (int g = 0; g < 8; g++) {
            float4 q = part[g][tid];
            s.x += q.x; s.y += q.y; s.z += q.z; s.w += q.w;
        }
        const float inv = inv_sh;
        s.x *= inv; s.y *= inv; s.z *= inv; s.w *= inv;
        reinterpret_cast<float4*>(g_ctx + b * D + ds * 128)[tid] = s;
    }
}

// ---------- Kernel D2: broadcast (write-bound, g_ctx L2-resident) ----------
__global__ void bcast_kernel(float4* __restrict__ out, int total4) {
    int i = blockIdx.x * 256 + threadIdx.x;
    if (i < total4)
        out[i] = reinterpret_cast<const float4*>(g_ctx)[i & (B * D / 4 - 1)];
}

extern "C" void kernel_launch(void* const* d_in, const int* in_sizes, int n_in,
                              void* d_out, int out_size) {
    // inputs: [0]=seqlen(int32), [1]=hidden f32 [1,B,H], [2]=contextvects f32 [B,D,C],
    //         [3]=W f32 [H,D], [4]=b f32 [H] (bias is softmax-invariant -> unused)
    const float* hid = (const float*)d_in[1];
    const float* ctx = (const float*)d_in[2];
    const float* W   = (const float*)d_in[3];

    vpart_kernel<<<dim3(8, HC), 128>>>(W, hid);
    vreduce_kernel<<<32, 256>>>();

    const size_t smemC = (size_t)(NSTAGE * TILE_F + 32 * 17 + 32) * sizeof(float); // ~199 KB
    cudaFuncSetAttribute(main_kernel, cudaFuncAttributeMaxDynamicSharedMemorySize, (int)smemC);
    main_kernel<<<dim3(NCHB, B), 1024, smemC>>>(ctx);

    combine_kernel<<<dim3(B, 8), 256>>>();

    const int total4 = out_size / 4;
    bcast_kernel<<<(total4 + 255) / 256, 256>>>((float4*)d_out, total4);
}

// round 10
// speedup vs baseline: 1.2642x; 1.2642x over previous
#include <cuda_runtime.h>

#define B    32
#define D    1024   // CTX_DIM
#define C    2048   // CTX_SIZE
#define H    1024   // HID
#define HC   32     // h-chunks in kernel A
#define HCH  (H/HC) // 32 h per chunk
#define CCH  16     // context columns per chunk
#define GCH  8      // chunks per CTA (flash-style running accumulation)
#define NCHB (C/(CCH*GCH))  // 16 CTA-columns per batch

// ---- scratch (no allocations allowed) ----
__device__ float g_pv[HC * B * D];       // 4 MB  partial v
__device__ float g_v[B * D];             // 128 KB v[b,d]
__device__ float g_pacc[B * NCHB * D];   // 2 MB per-CTA weighted partial sums
__device__ float g_pm[B * NCHB];         // per-CTA max
__device__ float g_pz[B * NCHB];         // per-CTA Z (unnormalized)
__device__ float g_ctx[B * D];           // final normalized context

// ---------- Kernel A: partial v[b,d] = sum_{h in chunk} W[h,d]*hidden[b,h] ----------
__global__ void vpart_kernel(const float* __restrict__ W, const float* __restrict__ hid) {
    __shared__ float sh[B][HCH];
    const int tid = threadIdx.x;                 // 128 threads
    const int d   = blockIdx.x * 128 + tid;      // 8 d-tiles
    const int h0  = blockIdx.y * HCH;            // 32 h-chunks
    for (int i = tid; i < B * HCH; i += 128) {
        int b = i / HCH, h = i % HCH;
        sh[b][h] = hid[b * H + h0 + h];
    }
    __syncthreads();
    float acc[B];
#pragma unroll
    for (int b = 0; b < B; b++) acc[b] = 0.f;
#pragma unroll 8
    for (int h = 0; h < HCH; h++) {
        float w = W[(size_t)(h0 + h) * D + d];
#pragma unroll
        for (int b = 0; b < B; b++) acc[b] += w * sh[b][h];
    }
    float* outp = g_pv + (size_t)blockIdx.y * (B * D);
#pragma unroll
    for (int b = 0; b < B; b++) outp[b * D + d] = acc[b];
}

// ---------- Kernel B: reduce partials -> g_v (float4, MLP 8) ----------
__global__ void vreduce_kernel() {
    int i = blockIdx.x * 256 + threadIdx.x;      // 32 blocks x 256 -> 8192 float4
    const float4* src = reinterpret_cast<const float4*>(g_pv) + i;
    float4 s = make_float4(0.f, 0.f, 0.f, 0.f);
#pragma unroll 8
    for (int hc = 0; hc < HC; hc++) {
        float4 p = src[(size_t)hc * (B * D / 4)];
        s.x += p.x; s.y += p.y; s.z += p.z; s.w += p.w;
    }
    reinterpret_cast<float4*>(g_v)[i] = s;
}

// ---------- Kernel C: R6 structure + deferred phase-2 lane reduction ----------
__global__ void __launch_bounds__(512, 2) main_kernel(const float* __restrict__ ctx) {
    __shared__ float red[16 * 17];      // padded: conflict-free column reads
    __shared__ float ws[16];
    __shared__ float m_sm, z_sm;

    const int tid  = threadIdx.x;       // 512
    const int lane = tid & 31;
    const int w    = tid >> 5;          // 0..15
    const int cq   = lane & 3;          // float4 column group 0..3
    const int r    = lane >> 2;         // 0..7
    const int b    = blockIdx.y;
    const int chg  = blockIdx.x;        // 0..NCHB-1

    const int drow = w * 8 + r;         // 0..127
    const float* base0 = ctx + (size_t)b * D * C + (size_t)drow * C
                       + chg * (CCH * GCH) + 4 * cq;

    float vr[8];
#pragma unroll
    for (int i = 0; i < 8; i++)
        vr[i] = __ldg(&g_v[b * D + i * 128 + drow]);

    float accR[8];                      // per-lane PARTIAL weighted sums (own 4 cols)
#pragma unroll
    for (int i = 0; i < 8; i++) accR[i] = 0.f;
    float m_run = -1e30f, z_run = 0.f;

    for (int g = 0; g < GCH; g++) {
        const float* base = base0 + g * CCH;
        float4 x[8];
#pragma unroll
        for (int i = 0; i < 8; i++)
            x[i] = __ldcs(reinterpret_cast<const float4*>(base + (size_t)i * 128 * C));

        // Phase 1: per-column partial scores
        float p0 = 0.f, p1 = 0.f, p2 = 0.f, p3 = 0.f;
#pragma unroll
        for (int i = 0; i < 8; i++) {
            p0 += x[i].x * vr[i];  p1 += x[i].y * vr[i];
            p2 += x[i].z * vr[i];  p3 += x[i].w * vr[i];
        }
#pragma unroll
        for (int o = 4; o <= 16; o <<= 1) {
            p0 += __shfl_xor_sync(0xffffffffu, p0, o);
            p1 += __shfl_xor_sync(0xffffffffu, p1, o);
            p2 += __shfl_xor_sync(0xffffffffu, p2, o);
            p3 += __shfl_xor_sync(0xffffffffu, p3, o);
        }
        if (lane < 4) {                 // r==0; cq==lane
            red[w * 17 + 4 * lane + 0] = p0;
            red[w * 17 + 4 * lane + 1] = p1;
            red[w * 17 + 4 * lane + 2] = p2;
            red[w * 17 + 4 * lane + 3] = p3;
        }
        __syncthreads();

        // lanes 0..15: finish 16 scores + chunk softmax stats (serial, as in R6)
        if (tid < 16) {
            float s = 0.f;
#pragma unroll
            for (int q = 0; q < 16; q++) s += red[q * 17 + tid];
            float m = s;
#pragma unroll
            for (int o = 8; o > 0; o >>= 1) m = fmaxf(m, __shfl_xor_sync(0x0000ffffu, m, o));
            float e = __expf(s - m);
            float z = e;
#pragma unroll
            for (int o = 8; o > 0; o >>= 1) z += __shfl_xor_sync(0x0000ffffu, z, o);
            ws[tid] = e;
            if (tid == 0) { m_sm = m; z_sm = z; }
        }
        __syncthreads();

        // Phase 2: per-lane weighted partials + running rescale (NO cross-lane work)
        const float w0 = ws[4 * cq + 0], w1 = ws[4 * cq + 1];
        const float w2 = ws[4 * cq + 2], w3 = ws[4 * cq + 3];
        const float m_g = m_sm, z_g = z_sm;
        const float m_new = fmaxf(m_run, m_g);
        const float alpha = __expf(m_run - m_new);
        const float beta  = __expf(m_g - m_new);
#pragma unroll
        for (int i = 0; i < 8; i++) {
            float t = x[i].x * w0 + x[i].y * w1 + x[i].z * w2 + x[i].w * w3;
            accR[i] = accR[i] * alpha + t * beta;
        }
        z_run = z_run * alpha + z_g * beta;
        m_run = m_new;
        // no further syncs: red/ws/m_sm writes next iter happen after next sync1
    }

    // Epilogue: reduce the deferred 4-lane (cq) partials once
#pragma unroll
    for (int i = 0; i < 8; i++) {
        accR[i] += __shfl_xor_sync(0xffffffffu, accR[i], 1);
        accR[i] += __shfl_xor_sync(0xffffffffu, accR[i], 2);
    }
    if (cq == 0) {
        float* dst = g_pacc + (size_t)(b * NCHB + chg) * D;
#pragma unroll
        for (int i = 0; i < 8; i++) dst[i * 128 + drow] = accR[i];
    }
    if (tid == 0) { g_pm[b * NCHB + chg] = m_run; g_pz[b * NCHB + chg] = z_run; }
}

// ---------- Kernel D1: single-stage combine -> g_ctx (as in R6) ----------
__global__ void combine_kernel() {
    __shared__ float pm[NCHB], pz[NCHB], fsh[NCHB];
    __shared__ float inv_sh;
    __shared__ float4 part[8][32];
    const int b   = blockIdx.x;
    const int ds  = blockIdx.y;            // 0..7  d-slice
    const int tid = threadIdx.x;           // 256
    const int f4  = tid & 31;              // float4 within slice
    const int grp = tid >> 5;              // 0..7 chunk group (2 chunks each)

    if (tid < NCHB) { pm[tid] = g_pm[b * NCHB + tid]; pz[tid] = g_pz[b * NCHB + tid]; }
    __syncthreads();
    if (tid < NCHB) {
        float M = -1e30f;
#pragma unroll
        for (int ch = 0; ch < NCHB; ch++) M = fmaxf(M, pm[ch]);
        fsh[tid] = __expf(pm[tid] - M);
        if (tid == 0) {
            float Z = 0.f;
#pragma unroll
            for (int ch = 0; ch < NCHB; ch++) Z += pz[ch] * __expf(pm[ch] - M);
            inv_sh = 1.0f / Z;
        }
    }
    __syncthreads();

    float4 a = make_float4(0.f, 0.f, 0.f, 0.f);
#pragma unroll
    for (int j = 0; j < 2; j++) {
        int ch = grp * 2 + j;
        float4 p = reinterpret_cast<const float4*>(
            g_pacc + (size_t)(b * NCHB + ch) * D + ds * 128)[f4];
        float f = fsh[ch];
        a.x += p.x * f; a.y += p.y * f; a.z += p.z * f; a.w += p.w * f;
    }
    part[grp][f4] = a;
    __syncthreads();

    if (tid < 32) {
        float4 s = make_float4(0.f, 0.f, 0.f, 0.f);
#pragma unroll
        for (int g = 0; g < 8; g++) {
            float4 p = part[g][tid];
            s.x += p.x; s.y += p.y; s.z += p.z; s.w += p.w;
        }
        const float inv = inv_sh;
        s.x *= inv; s.y *= inv; s.z *= inv; s.w *= inv;
        reinterpret_cast<float4*>(g_ctx + b * D + ds * 128)[tid] = s;
    }
}

// ---------- Kernel D2: broadcast over seqlen (write-bound, g_ctx L2-resident) ----------
__global__ void bcast_kernel(float4* __restrict__ out, int total4) {
    int i = blockIdx.x * 256 + threadIdx.x;
    if (i < total4)
        out[i] = reinterpret_cast<const float4*>(g_ctx)[i & (B * D / 4 - 1)];
}

extern "C" void kernel_launch(void* const* d_in, const int* in_sizes, int n_in,
                              void* d_out, int out_size) {
    // inputs: [0]=seqlen(int32), [1]=hidden f32 [1,B,H], [2]=contextvects f32 [B,D,C],
    //         [3]=W f32 [H,D], [4]=b f32 [H] (bias is softmax-invariant -> unused)
    const float* hid = (const float*)d_in[1];
    const float* ctx = (const float*)d_in[2];
    const float* W   = (const float*)d_in[3];

    vpart_kernel<<<dim3(8, HC), 128>>>(W, hid);
    vreduce_kernel<<<32, 256>>>();

    main_kernel<<<dim3(NCHB, B), 512>>>(ctx);

    combine_kernel<<<dim3(B, 8), 256>>>();

    const int total4 = out_size / 4;
    bcast_kernel<<<(total4 + 255) / 256, 256>>>((float4*)d_out, total4);
}